// round 12
// baseline (speedup 1.0000x reference)
#include <cuda_runtime.h>
#include <cuda_bf16.h>
#include <cstdint>

// ---------------------------------------------------------------------------
// CopyNet pointer-generator mix, fused, vocab-chunked.
//   out[b,t,v] = p_gen[b,t] * (v < V ? dist[b,t,v] : 0)
//              + (1 - p_gen[b,t]) * sum_{s: pointer[b,s]==v} alph[b,s,t]
//
// Proven launch shape (R5): one CTA per (row, chunk), NCHUNK=8, 256 threads,
// 16.06 KB smem -> 8 CTAs/SM. Added vs R5: phase-3 4-deep front-batched
// unroll (MLP 4->16) and __ldcs streaming loads for dist.
// ---------------------------------------------------------------------------

#define NCHUNK 8
#define TPB    256

__global__ __launch_bounds__(TPB)
void copynet_fused_chunk_kernel(const float* __restrict__ dist,
                                const float* __restrict__ p_gen,
                                const float* __restrict__ alph,
                                const int*   __restrict__ pointer,
                                float* __restrict__ out,
                                int V4, int Vext4, int chunk4,
                                int L_DEC, int L_SRC)
{
    extern __shared__ float srow[];            // chunk4*4 floats
    float4* s4 = reinterpret_cast<float4*>(srow);

    int row   = blockIdx.x / NCHUNK;           // b*L_DEC + t
    int chunk = blockIdx.x - row * NCHUNK;
    int b     = row / L_DEC;
    int t     = row - b * L_DEC;

    int lo = chunk * (chunk4 * 4);             // vocab range [lo, hi) for this CTA
    int hi = lo + chunk4 * 4;

    float pg    = __ldg(&p_gen[row]);
    float one_m = 1.0f - pg;

    // Phase 1: zero the shared accumulator chunk.
    float4 z = make_float4(0.f, 0.f, 0.f, 0.f);
    for (int i = threadIdx.x; i < chunk4; i += TPB)
        s4[i] = z;
    __syncthreads();

    // Phase 2: scan the row's L_SRC (pointer, alpha) pairs; scatter hits
    // into shared. (Identical to the passing R5 kernel.)
    {
        const float* arow = alph + ((size_t)b * L_SRC) * L_DEC + t;
        const int*   prow = pointer + b * L_SRC;
        for (int s = threadIdx.x; s < L_SRC; s += TPB) {
            int p = __ldg(&prow[s]);
            if (p >= lo && p < hi) {
                float a = __ldg(&arow[(size_t)s * L_DEC]);
                atomicAdd(&srow[p - lo], one_m * a);
            }
        }
    }
    __syncthreads();

    // Phase 3: fused stream: out = pg*dist (+ pad zeros) + copyp.
    // 4-deep unroll with the four independent LDG.128s issued back-to-back
    // before any consume -> higher per-warp MLP for DRAM latency hiding.
    {
        int base4 = chunk * chunk4;            // float4 offset within the row
        const float4* src = reinterpret_cast<const float4*>(dist) + (size_t)row * V4;
        float4*       dst = reinterpret_cast<float4*>(out) + (size_t)row * Vext4 + base4;

        for (int i0 = threadIdx.x; i0 < chunk4; i0 += 4 * TPB) {
            if (i0 + 3 * TPB < chunk4 && base4 + i0 + 3 * TPB < V4) {
                // Steady state: branch-free, loads batched first.
                float4 d[4], c[4];
                #pragma unroll
                for (int k = 0; k < 4; k++)
                    d[k] = __ldcs(&src[base4 + i0 + k * TPB]);
                #pragma unroll
                for (int k = 0; k < 4; k++)
                    c[k] = s4[i0 + k * TPB];
                #pragma unroll
                for (int k = 0; k < 4; k++) {
                    c[k].x = fmaf(pg, d[k].x, c[k].x);
                    c[k].y = fmaf(pg, d[k].y, c[k].y);
                    c[k].z = fmaf(pg, d[k].z, c[k].z);
                    c[k].w = fmaf(pg, d[k].w, c[k].w);
                    dst[i0 + k * TPB] = c[k];
                }
            } else {
                // Tail: predicated per-slot (chunk end + vocab pad region).
                #pragma unroll
                for (int k = 0; k < 4; k++) {
                    int i = i0 + k * TPB;
                    if (i < chunk4) {
                        float4 c = s4[i];
                        int g = base4 + i;
                        if (g < V4) {
                            float4 d = __ldcs(&src[g]);
                            c.x = fmaf(pg, d.x, c.x);
                            c.y = fmaf(pg, d.y, c.y);
                            c.z = fmaf(pg, d.z, c.z);
                            c.w = fmaf(pg, d.w, c.w);
                        }
                        dst[i] = c;
                    }
                }
            }
        }
    }
}

// Fallback: full-row-in-smem fused kernel (scalar), for odd shapes.
__global__ void copynet_fused_scalar_kernel(const float* __restrict__ dist,
                                            const float* __restrict__ p_gen,
                                            const float* __restrict__ alph,
                                            const int*   __restrict__ pointer,
                                            float* __restrict__ out,
                                            int V, int Vext,
                                            int L_DEC, int L_SRC)
{
    extern __shared__ float srow[];
    int row = blockIdx.x;
    int b   = row / L_DEC;
    int t   = row - b * L_DEC;
    float pg = __ldg(&p_gen[row]);
    float one_m = 1.0f - pg;

    for (int i = threadIdx.x; i < Vext; i += blockDim.x)
        srow[i] = 0.f;
    __syncthreads();

    const float* arow = alph + ((size_t)b * L_SRC) * L_DEC + t;
    const int*   prow = pointer + b * L_SRC;
    for (int s = threadIdx.x; s < L_SRC; s += blockDim.x)
        atomicAdd(&srow[__ldg(&prow[s])], one_m * __ldg(&arow[(size_t)s * L_DEC]));
    __syncthreads();

    for (int i = threadIdx.x; i < Vext; i += blockDim.x) {
        float c = srow[i];
        if (i < V) c = fmaf(pg, __ldg(&dist[(size_t)row * V + i]), c);
        out[(size_t)row * Vext + i] = c;
    }
}

extern "C" void kernel_launch(void* const* d_in, const int* in_sizes, int n_in,
                              void* d_out, int out_size)
{
    // metadata order: dist_t, p_gen, alph_t, batch_vocab, pointer
    const float* dist    = (const float*)d_in[0];
    const float* p_gen   = (const float*)d_in[1];
    const float* alph    = (const float*)d_in[2];
    const int*   pointer = (const int*)d_in[4];
    float*       out     = (float*)d_out;

    int BT    = in_sizes[1];                 // B * L_DEC   (2048)
    int Vext  = in_sizes[3];                 // 32128
    int BS    = in_sizes[4];                 // B * L_SRC   (4096)
    int L_DEC = in_sizes[2] / BS;            // 256
    int B     = BT / L_DEC;                  // 8
    int L_SRC = BS / B;                      // 512
    int V     = in_sizes[0] / BT;            // 32000

    bool vec_ok = (V % 4 == 0) && (Vext % (4 * NCHUNK) == 0);

    if (vec_ok) {
        int V4     = V / 4;
        int Vext4  = Vext / 4;
        int chunk4 = Vext4 / NCHUNK;          // 1004 float4 = 16.06 KB
        size_t smem_bytes = (size_t)chunk4 * 4 * sizeof(float);
        cudaFuncSetAttribute(copynet_fused_chunk_kernel,
                             cudaFuncAttributeMaxDynamicSharedMemorySize,
                             (int)smem_bytes);
        copynet_fused_chunk_kernel<<<BT * NCHUNK, TPB, smem_bytes>>>(
            dist, p_gen, alph, pointer, out, V4, Vext4, chunk4, L_DEC, L_SRC);
    } else {
        size_t smem_bytes = (size_t)Vext * sizeof(float);
        cudaFuncSetAttribute(copynet_fused_scalar_kernel,
                             cudaFuncAttributeMaxDynamicSharedMemorySize,
                             (int)smem_bytes);
        copynet_fused_scalar_kernel<<<BT, 1024, smem_bytes>>>(
            dist, p_gen, alph, pointer, out, V, Vext, L_DEC, L_SRC);
    }
}